// round 13
// baseline (speedup 1.0000x reference)
#include <cuda_runtime.h>
#include <cstdint>

// DeepSeekMoEFFN (sm_103 plain PTX: no tcgen05) — mma.sync tf32 GEMMs with
// ldmatrix fragment loads, 64x64 warp tiles, 4-stage cp.async pipeline.
//
//  1. gate (fp64 argmax) -> expert ids + counts
//  2. counting-sort -> perm
//  3. prep: gather+rna(x); transpose+rna weights to K-major [e][n][k];
//     bias1=[b1_e|sb1]; bias2 = b2_0+b2_1+sb2+relu(b1_o)@w2_o
//  4. GEMM1: h = rna(relu(xs @ B1_e + bias1_e))   [16384 x 8192]
//  5. GEMM2: out[perm] = h @ B2_e + bias2_e       [16384 x 1024]

#define N_TOK  16384
#define DMODEL 1024
#define HID    4096
#define HCAT   8192

#define BM 128
#define BN 256
#define BK 32
#define STAGES 4
#define LDK 36                        // padded k-stride (floats), conflict-free
#define A_STG (BM * LDK)              // 4608 floats
#define B_STG (BN * LDK)              // 9216 floats
#define GEMM_SMEM (STAGES * (A_STG + B_STG) * 4)   // 221184 B

// ---- static device scratch ----
__device__ float g_h [(size_t)N_TOK * HCAT];
__device__ float g_xr[(size_t)N_TOK * DMODEL];
__device__ float g_B1[(size_t)2 * HCAT * DMODEL];  // [e][n][k] K-major, rounded
__device__ float g_B2[(size_t)2 * DMODEL * HCAT];  // [e][n][k] K-major, rounded
__device__ float g_bias1[2 * HCAT];
__device__ float g_bias2[2 * DMODEL];
__device__ int   g_expert[N_TOK];
__device__ int   g_perm[N_TOK];
__device__ int   g_counts[2];
__device__ int   g_cursor[2];

// ---------------- helpers ----------------
__device__ __forceinline__ float rna_tf32(float f) {
    uint32_t u;
    asm("cvt.rna.tf32.f32 %0, %1;" : "=r"(u) : "f"(f));
    return __uint_as_float(u);
}
__device__ __forceinline__ void mma_tf32(float4& d, const uint32_t* a, const uint32_t* b) {
    asm volatile(
        "mma.sync.aligned.m16n8k8.row.col.f32.tf32.tf32.f32 "
        "{%0,%1,%2,%3}, {%4,%5,%6,%7}, {%8,%9}, {%0,%1,%2,%3};"
        : "+f"(d.x), "+f"(d.y), "+f"(d.z), "+f"(d.w)
        : "r"(a[0]), "r"(a[1]), "r"(a[2]), "r"(a[3]),
          "r"(b[0]), "r"(b[1]));
}
__device__ __forceinline__ void cp_async16(uint32_t s, const void* g) {
    asm volatile("cp.async.cg.shared.global [%0], [%1], 16;" :: "r"(s), "l"(g));
}
#define CP_COMMIT() asm volatile("cp.async.commit_group;" ::: "memory")
#define CP_WAIT2()  asm volatile("cp.async.wait_group 2;" ::: "memory")
#define LDSM4(r, a) \
    asm volatile("ldmatrix.sync.aligned.m8n8.x4.shared.b16 {%0,%1,%2,%3}, [%4];" \
        : "=r"((r)[0]), "=r"((r)[1]), "=r"((r)[2]), "=r"((r)[3]) : "r"(a))

// ---------------- routing / prep ----------------
__global__ void zero_kernel() {
    if (threadIdx.x == 0) { g_counts[0] = g_counts[1] = 0; g_cursor[0] = g_cursor[1] = 0; }
}

__global__ void gate_kernel(const float* __restrict__ x, const float* __restrict__ gw) {
    int t = blockIdx.x * (blockDim.x >> 5) + (threadIdx.x >> 5);
    if (t >= N_TOK) return;
    int lane = threadIdx.x & 31;
    const float* xr = x + (size_t)t * DMODEL;
    double s0 = 0.0, s1 = 0.0;
    for (int k = lane; k < DMODEL; k += 32) {
        double xv = (double)xr[k];
        s0 += xv * (double)gw[k];
        s1 += xv * (double)gw[DMODEL + k];
    }
    #pragma unroll
    for (int o = 16; o > 0; o >>= 1) {
        s0 += __shfl_down_sync(0xffffffffu, s0, o);
        s1 += __shfl_down_sync(0xffffffffu, s1, o);
    }
    if (lane == 0) {
        int e = (s1 > s0) ? 1 : 0;
        g_expert[t] = e;
        atomicAdd(&g_counts[e], 1);
    }
}

__global__ void scatter_kernel() {
    int t = blockIdx.x * blockDim.x + threadIdx.x;
    if (t >= N_TOK) return;
    int e = g_expert[t];
    int base = e ? g_counts[0] : 0;
    g_perm[base + atomicAdd(&g_cursor[e], 1)] = t;
}

__global__ void prep_x_kernel(const float* __restrict__ x) {
    const float4* x4 = reinterpret_cast<const float4*>(x);
    float4* d4 = reinterpret_cast<float4*>(g_xr);
    const int total = N_TOK * (DMODEL / 4);
    for (int i = blockIdx.x * blockDim.x + threadIdx.x; i < total;
         i += gridDim.x * blockDim.x) {
        int pos = i >> 8, c4 = i & 255;
        int src = g_perm[pos];
        float4 v = x4[(size_t)src * 256 + c4];
        v.x = rna_tf32(v.x); v.y = rna_tf32(v.y);
        v.z = rna_tf32(v.z); v.w = rna_tf32(v.w);
        d4[i] = v;
    }
}

// B1t[e][n][k] = rna( n<HID ? w1[e][k][n] : sw1[k][n-HID] )
__global__ void prep_B1t_kernel(const float* __restrict__ w1, const float* __restrict__ sw1) {
    __shared__ float t[32][33];
    int n0 = blockIdx.x * 32, k0 = blockIdx.y * 32, e = blockIdx.z;
    int tx = threadIdx.x & 31, ty = threadIdx.x >> 5;
    int n = n0 + tx;
    #pragma unroll
    for (int p = 0; p < 4; p++) {
        int k = k0 + ty + p * 8;
        float v = (n < HID) ? w1[((size_t)e * DMODEL + k) * HID + n]
                            : sw1[(size_t)k * HID + (n - HID)];
        t[ty + p * 8][tx] = rna_tf32(v);
    }
    __syncthreads();
    #pragma unroll
    for (int p = 0; p < 4; p++) {
        int ni = ty + p * 8;
        g_B1[((size_t)e * HCAT + n0 + ni) * DMODEL + k0 + tx] = t[tx][ni];
    }
}

// B2t[e][n][k] = rna( k<HID ? w2[e][k][n] : sw2[k-HID][n] )
__global__ void prep_B2t_kernel(const float* __restrict__ w2, const float* __restrict__ sw2) {
    __shared__ float t[32][33];
    int n0 = blockIdx.x * 32, k0 = blockIdx.y * 32, e = blockIdx.z;
    int tx = threadIdx.x & 31, ty = threadIdx.x >> 5;
    int n = n0 + tx;
    #pragma unroll
    for (int p = 0; p < 4; p++) {
        int k = k0 + ty + p * 8;
        float v = (k < HID) ? w2[((size_t)e * HID + k) * DMODEL + n]
                            : sw2[(size_t)(k - HID) * DMODEL + n];
        t[ty + p * 8][tx] = rna_tf32(v);
    }
    __syncthreads();
    #pragma unroll
    for (int p = 0; p < 4; p++) {
        int ni = ty + p * 8;
        g_B2[((size_t)e * DMODEL + n0 + ni) * HCAT + k0 + tx] = t[tx][ni];
    }
}

__global__ void prep_bias1_kernel(const float* __restrict__ b1, const float* __restrict__ sb1) {
    int i = blockIdx.x * blockDim.x + threadIdx.x;
    if (i >= 2 * HCAT) return;
    int e = i >> 13, n = i & (HCAT - 1);
    g_bias1[i] = (n < HID) ? b1[e * HID + n] : sb1[n - HID];
}

// bias2[e][n] = b2[e][n] + b2[1-e][n] + sb2[n] + relu(b1[1-e]) @ w2[1-e][:,n]
__global__ void prep_bias2_kernel(const float* __restrict__ b1, const float* __restrict__ b2,
                                  const float* __restrict__ w2, const float* __restrict__ sb2) {
    int i = blockIdx.x * blockDim.x + threadIdx.x;
    if (i >= 2 * DMODEL) return;
    int e = i >> 10, n = i & (DMODEL - 1);
    int o = 1 - e;
    const float* w2o = w2 + (size_t)o * HID * DMODEL;
    const float* b1o = b1 + o * HID;
    float acc = 0.f;
    for (int k = 0; k < HID; k++)
        acc = fmaf(fmaxf(b1o[k], 0.f), w2o[(size_t)k * DMODEL + n], acc);
    g_bias2[i] = b2[e * DMODEL + n] + b2[o * DMODEL + n] + sb2[n] + acc;
}

// ------------------------------------------------------------------
// 128x256x32 tf32 mma.sync GEMM: 8 warps (2m x 4n), 64x64 warp tiles,
// ldmatrix.x4 fragment loads, 4-stage cp.async pipeline, 1 CTA/SM.
template <int K, int NT, bool G1>
__global__ void __launch_bounds__(256, 1)
gemm_cp(float* __restrict__ out_g2) {
    // CTA raster swizzle: groups of 16 m-tiles, m fastest
    const int bid = blockIdx.y * gridDim.x + blockIdx.x;
    const int per = gridDim.x * 16;
    const int mt  = (bid / per) * 16 + (bid % 16);
    const int j   = (bid % per) >> 4;

    const int c0 = g_counts[0];
    const int c1 = N_TOK - c0;
    const int t0 = (c0 + BM - 1) / BM;
    const int t1 = (c1 + BM - 1) / BM;
    int expert, row0, valid;
    if (mt < t0)           { expert = 0; row0 = mt * BM;            valid = min(BM, c0 - row0); }
    else if (mt - t0 < t1) { int t = mt - t0; expert = 1; row0 = c0 + t * BM; valid = min(BM, c1 - t * BM); }
    else return;

    const float* __restrict__ A    = G1 ? g_xr : g_h;
    const float* __restrict__ Bt   = G1 ? g_B1 : g_B2;
    const float* __restrict__ bias = G1 ? g_bias1 : g_bias2;
    const int n0 = j * BN;
    const float* __restrict__ Bp = Bt + ((size_t)expert * NT + n0) * K;

    extern __shared__ float smem[];
    float* sA = smem;                      // [STAGES][BM][LDK]
    float* sB = smem + STAGES * A_STG;     // [STAGES][BN][LDK]
    const uint32_t sAu = (uint32_t)__cvta_generic_to_shared(sA);
    const uint32_t sBu = (uint32_t)__cvta_generic_to_shared(sB);

    const int tid = threadIdx.x, lane = tid & 31, warp = tid >> 5;
    const int wm = warp & 1;    // 2 warps over M (64 rows)
    const int wn = warp >> 1;   // 4 warps over N (64 cols)

    // per-stage fill: A 128x32f (4x16B/thr), B 256x32f (8x16B/thr)
    auto load_tile = [&](int kt, int stage) {
        const int kof = kt * BK;
        const uint32_t aB = sAu + stage * (A_STG * 4);
        const uint32_t bB = sBu + stage * (B_STG * 4);
        #pragma unroll
        for (int p = 0; p < 4; p++) {
            int idx = tid + p * 256;             // 0..1023
            int r = idx >> 3, c4 = idx & 7;
            int rg = row0 + r; if (rg > N_TOK - 1) rg = N_TOK - 1;
            cp_async16(aB + (uint32_t)(r * (LDK * 4) + c4 * 16),
                       A + (size_t)rg * K + kof + c4 * 4);
        }
        #pragma unroll
        for (int p = 0; p < 8; p++) {
            int idx = tid + p * 256;             // 0..2047
            int r = idx >> 3, c4 = idx & 7;
            cp_async16(bB + (uint32_t)(r * (LDK * 4) + c4 * 16),
                       Bp + (size_t)r * K + kof + c4 * 4);
        }
        CP_COMMIT();
    };

    constexpr int KT = K / BK;
    load_tile(0, 0);
    load_tile(1, 1);
    load_tile(2, 2);

    float4 acc[4][8];
    #pragma unroll
    for (int i = 0; i < 4; i++)
        #pragma unroll
        for (int jn = 0; jn < 8; jn++)
            acc[i][jn] = make_float4(0.f, 0.f, 0.f, 0.f);

    // ldmatrix per-thread addressing
    //   A x4: matrices [m0-7|k0-3],[m8-15|k0-3],[m0-7|k4-7],[m8-15|k4-7] -> a0..a3
    //   B x4: matrices [n0-7|k0-3],[n0-7|k4-7],[n8-15|k0-3],[n8-15|k4-7]
    const int mA = lane & 15;
    const int kA = (lane >> 4) * 4;
    const int nB = (lane & 7) + ((lane >> 4) << 3);
    const int kB = ((lane >> 3) & 1) * 4;
    const uint32_t aBase = sAu + (uint32_t)(((wm * 64 + mA) * LDK + kA) * 4);
    const uint32_t bBase = sBu + (uint32_t)(((wn * 64 + nB) * LDK + kB) * 4);

    #pragma unroll 1
    for (int kt = 0; kt < KT; kt++) {
        CP_WAIT2();
        __syncthreads();
        if (kt + 3 < KT) load_tile(kt + 3, (kt + 3) & (STAGES - 1));
        else             CP_COMMIT();        // keep group counting uniform

        const uint32_t aS = aBase + (uint32_t)((kt & (STAGES - 1)) * (A_STG * 4));
        const uint32_t bS = bBase + (uint32_t)((kt & (STAGES - 1)) * (B_STG * 4));
        #pragma unroll
        for (int ks = 0; ks < 4; ks++) {
            uint32_t af[4][4], bf[4][4];
            #pragma unroll
            for (int m = 0; m < 4; m++)
                LDSM4(af[m], aS + (uint32_t)(m * (16 * LDK * 4) + ks * 32));
            #pragma unroll
            for (int np = 0; np < 4; np++)
                LDSM4(bf[np], bS + (uint32_t)(np * (16 * LDK * 4) + ks * 32));
            #pragma unroll
            for (int m = 0; m < 4; m++)
                #pragma unroll
                for (int nt = 0; nt < 8; nt++)
                    mma_tf32(acc[m][nt], af[m], &bf[nt >> 1][(nt & 1) * 2]);
        }
    }

    // epilogue
    const float* bv = bias + (size_t)expert * NT + n0;
    const int grow = lane >> 2;
    const int gc   = (lane & 3) << 1;
    #pragma unroll
    for (int m = 0; m < 4; m++) {
        int rl = wm * 64 + m * 16 + grow;
        #pragma unroll
        for (int nt = 0; nt < 8; nt++) {
            int cl = wn * 64 + nt * 8 + gc;
            float bb0 = bv[cl], bb1 = bv[cl + 1];
            float v00 = acc[m][nt].x + bb0;
            float v01 = acc[m][nt].y + bb1;
            float v10 = acc[m][nt].z + bb0;
            float v11 = acc[m][nt].w + bb1;
            if constexpr (G1) {
                v00 = rna_tf32(fmaxf(v00, 0.f));
                v01 = rna_tf32(fmaxf(v01, 0.f));
                v10 = rna_tf32(fmaxf(v10, 0.f));
                v11 = rna_tf32(fmaxf(v11, 0.f));
                if (rl < valid) {
                    float2 v = {v00, v01};
                    *reinterpret_cast<float2*>(&g_h[(size_t)(row0 + rl) * HCAT + n0 + cl]) = v;
                }
                if (rl + 8 < valid) {
                    float2 v = {v10, v11};
                    *reinterpret_cast<float2*>(&g_h[(size_t)(row0 + rl + 8) * HCAT + n0 + cl]) = v;
                }
            } else {
                if (rl < valid) {
                    int orow = g_perm[row0 + rl];
                    float2 v = {v00, v01};
                    *reinterpret_cast<float2*>(&out_g2[(size_t)orow * DMODEL + n0 + cl]) = v;
                }
                if (rl + 8 < valid) {
                    int orow = g_perm[row0 + rl + 8];
                    float2 v = {v10, v11};
                    *reinterpret_cast<float2*>(&out_g2[(size_t)orow * DMODEL + n0 + cl]) = v;
                }
            }
        }
    }
}

// ---------------- launch ----------------
extern "C" void kernel_launch(void* const* d_in, const int* in_sizes, int n_in,
                              void* d_out, int out_size) {
    const float* x   = (const float*)d_in[0];
    const float* gw  = (const float*)d_in[1];
    const float* w1  = (const float*)d_in[2];
    const float* b1  = (const float*)d_in[3];
    const float* w2  = (const float*)d_in[4];
    const float* b2  = (const float*)d_in[5];
    const float* sw1 = (const float*)d_in[6];
    const float* sb1 = (const float*)d_in[7];
    const float* sw2 = (const float*)d_in[8];
    const float* sb2 = (const float*)d_in[9];
    float* out = (float*)d_out;

    cudaFuncSetAttribute((const void*)gemm_cp<DMODEL, HCAT, true>,
                         cudaFuncAttributeMaxDynamicSharedMemorySize, GEMM_SMEM);
    cudaFuncSetAttribute((const void*)gemm_cp<HCAT, DMODEL, false>,
                         cudaFuncAttributeMaxDynamicSharedMemorySize, GEMM_SMEM);

    zero_kernel<<<1, 32>>>();
    gate_kernel<<<N_TOK / 8, 256>>>(x, gw);
    scatter_kernel<<<N_TOK / 256, 256>>>();
    prep_x_kernel<<<2048, 256>>>(x);
    prep_B1t_kernel<<<dim3(HCAT / 32, DMODEL / 32, 2), 256>>>(w1, sw1);
    prep_B2t_kernel<<<dim3(DMODEL / 32, HCAT / 32, 2), 256>>>(w2, sw2);
    prep_bias1_kernel<<<(2 * HCAT) / 256, 256>>>(b1, sb1);
    prep_bias2_kernel<<<(2 * DMODEL) / 256, 256>>>(b1, b2, w2, sb2);

    // 129 m-tiles padded to 144 (9 swizzle groups of 16); extras exit early
    gemm_cp<DMODEL, HCAT, true ><<<dim3(HCAT / BN,   144), 256, GEMM_SMEM>>>(nullptr);
    gemm_cp<HCAT, DMODEL, false><<<dim3(DMODEL / BN, 144), 256, GEMM_SMEM>>>(out);
}

// round 14
// speedup vs baseline: 1.5092x; 1.5092x over previous
#include <cuda_runtime.h>
#include <cuda_fp16.h>
#include <cstdint>

// DeepSeekMoEFFN (sm_103 plain PTX: no tcgen05) — fp16 mma.sync m16n8k16
// GEMMs (fp32 accumulate), ldmatrix fragments, 4-stage cp.async pipeline.
//
//  1. gate (fp64 argmax) -> expert ids + counts
//  2. counting-sort -> perm
//  3. prep: gather x -> fp16; transpose weights to K-major [e][n][k] fp16;
//     bias1=[b1_e|sb1]; bias2 = b2_0+b2_1+sb2+relu(b1_o)@w2_o   (fp32)
//  4. GEMM1: h = fp16(relu(xs @ B1_e + bias1_e))   [16384 x 8192]
//  5. GEMM2: out[perm] = h @ B2_e + bias2_e        [16384 x 1024] fp32

#define N_TOK  16384
#define DMODEL 1024
#define HID    4096
#define HCAT   8192

#define BM 128
#define BN 256
#define BK 32
#define STAGES 4
#define LDK 40                        // padded k-stride in halves (80 B rows)
#define A_STG (BM * LDK)              // halves
#define B_STG (BN * LDK)              // halves
#define GEMM_SMEM (STAGES * (A_STG + B_STG) * 2)   // 122880 B

// ---- static device scratch ----
__device__ __half g_h [(size_t)N_TOK * HCAT];       // fp16 intermediate (256MB)
__device__ __half g_xr[(size_t)N_TOK * DMODEL];     // sorted fp16 x
__device__ __half g_B1[(size_t)2 * HCAT * DMODEL];  // [e][n][k] K-major fp16
__device__ __half g_B2[(size_t)2 * DMODEL * HCAT];  // [e][n][k] K-major fp16
__device__ float  g_bias1[2 * HCAT];
__device__ float  g_bias2[2 * DMODEL];
__device__ int    g_expert[N_TOK];
__device__ int    g_perm[N_TOK];
__device__ int    g_counts[2];
__device__ int    g_cursor[2];

// ---------------- helpers ----------------
__device__ __forceinline__ void mma_f16(float4& d, const uint32_t* a, const uint32_t* b) {
    asm volatile(
        "mma.sync.aligned.m16n8k16.row.col.f32.f16.f16.f32 "
        "{%0,%1,%2,%3}, {%4,%5,%6,%7}, {%8,%9}, {%0,%1,%2,%3};"
        : "+f"(d.x), "+f"(d.y), "+f"(d.z), "+f"(d.w)
        : "r"(a[0]), "r"(a[1]), "r"(a[2]), "r"(a[3]),
          "r"(b[0]), "r"(b[1]));
}
__device__ __forceinline__ void cp_async16(uint32_t s, const void* g) {
    asm volatile("cp.async.cg.shared.global [%0], [%1], 16;" :: "r"(s), "l"(g));
}
#define CP_COMMIT() asm volatile("cp.async.commit_group;" ::: "memory")
#define CP_WAIT2()  asm volatile("cp.async.wait_group 2;" ::: "memory")
#define LDSM4(r, a) \
    asm volatile("ldmatrix.sync.aligned.m8n8.x4.shared.b16 {%0,%1,%2,%3}, [%4];" \
        : "=r"((r)[0]), "=r"((r)[1]), "=r"((r)[2]), "=r"((r)[3]) : "r"(a))

// ---------------- routing / prep ----------------
__global__ void zero_kernel() {
    if (threadIdx.x == 0) { g_counts[0] = g_counts[1] = 0; g_cursor[0] = g_cursor[1] = 0; }
}

__global__ void gate_kernel(const float* __restrict__ x, const float* __restrict__ gw) {
    int t = blockIdx.x * (blockDim.x >> 5) + (threadIdx.x >> 5);
    if (t >= N_TOK) return;
    int lane = threadIdx.x & 31;
    const float* xr = x + (size_t)t * DMODEL;
    double s0 = 0.0, s1 = 0.0;
    for (int k = lane; k < DMODEL; k += 32) {
        double xv = (double)xr[k];
        s0 += xv * (double)gw[k];
        s1 += xv * (double)gw[DMODEL + k];
    }
    #pragma unroll
    for (int o = 16; o > 0; o >>= 1) {
        s0 += __shfl_down_sync(0xffffffffu, s0, o);
        s1 += __shfl_down_sync(0xffffffffu, s1, o);
    }
    if (lane == 0) {
        int e = (s1 > s0) ? 1 : 0;
        g_expert[t] = e;
        atomicAdd(&g_counts[e], 1);
    }
}

__global__ void scatter_kernel() {
    int t = blockIdx.x * blockDim.x + threadIdx.x;
    if (t >= N_TOK) return;
    int e = g_expert[t];
    int base = e ? g_counts[0] : 0;
    g_perm[base + atomicAdd(&g_cursor[e], 1)] = t;
}

__global__ void prep_x_kernel(const float* __restrict__ x) {
    const float4* x4 = reinterpret_cast<const float4*>(x);
    __half2* d2 = reinterpret_cast<__half2*>(g_xr);
    const int total = N_TOK * (DMODEL / 4);
    for (int i = blockIdx.x * blockDim.x + threadIdx.x; i < total;
         i += gridDim.x * blockDim.x) {
        int pos = i >> 8, c4 = i & 255;
        int src = g_perm[pos];
        float4 v = x4[(size_t)src * 256 + c4];
        d2[2 * i]     = __floats2half2_rn(v.x, v.y);
        d2[2 * i + 1] = __floats2half2_rn(v.z, v.w);
    }
}

// B1t[e][n][k] = fp16( n<HID ? w1[e][k][n] : sw1[k][n-HID] )
__global__ void prep_B1t_kernel(const float* __restrict__ w1, const float* __restrict__ sw1) {
    __shared__ float t[32][33];
    int n0 = blockIdx.x * 32, k0 = blockIdx.y * 32, e = blockIdx.z;
    int tx = threadIdx.x & 31, ty = threadIdx.x >> 5;
    int n = n0 + tx;
    #pragma unroll
    for (int p = 0; p < 4; p++) {
        int k = k0 + ty + p * 8;
        float v = (n < HID) ? w1[((size_t)e * DMODEL + k) * HID + n]
                            : sw1[(size_t)k * HID + (n - HID)];
        t[ty + p * 8][tx] = v;
    }
    __syncthreads();
    #pragma unroll
    for (int p = 0; p < 4; p++) {
        int ni = ty + p * 8;
        g_B1[((size_t)e * HCAT + n0 + ni) * DMODEL + k0 + tx] = __float2half_rn(t[tx][ni]);
    }
}

// B2t[e][n][k] = fp16( k<HID ? w2[e][k][n] : sw2[k-HID][n] )
__global__ void prep_B2t_kernel(const float* __restrict__ w2, const float* __restrict__ sw2) {
    __shared__ float t[32][33];
    int n0 = blockIdx.x * 32, k0 = blockIdx.y * 32, e = blockIdx.z;
    int tx = threadIdx.x & 31, ty = threadIdx.x >> 5;
    int n = n0 + tx;
    #pragma unroll
    for (int p = 0; p < 4; p++) {
        int k = k0 + ty + p * 8;
        float v = (k < HID) ? w2[((size_t)e * HID + k) * DMODEL + n]
                            : sw2[(size_t)(k - HID) * DMODEL + n];
        t[ty + p * 8][tx] = v;
    }
    __syncthreads();
    #pragma unroll
    for (int p = 0; p < 4; p++) {
        int ni = ty + p * 8;
        g_B2[((size_t)e * DMODEL + n0 + ni) * HCAT + k0 + tx] = __float2half_rn(t[tx][ni]);
    }
}

__global__ void prep_bias1_kernel(const float* __restrict__ b1, const float* __restrict__ sb1) {
    int i = blockIdx.x * blockDim.x + threadIdx.x;
    if (i >= 2 * HCAT) return;
    int e = i >> 13, n = i & (HCAT - 1);
    g_bias1[i] = (n < HID) ? b1[e * HID + n] : sb1[n - HID];
}

// bias2[e][n] = b2[e][n] + b2[1-e][n] + sb2[n] + relu(b1[1-e]) @ w2[1-e][:,n]
__global__ void prep_bias2_kernel(const float* __restrict__ b1, const float* __restrict__ b2,
                                  const float* __restrict__ w2, const float* __restrict__ sb2) {
    int i = blockIdx.x * blockDim.x + threadIdx.x;
    if (i >= 2 * DMODEL) return;
    int e = i >> 10, n = i & (DMODEL - 1);
    int o = 1 - e;
    const float* w2o = w2 + (size_t)o * HID * DMODEL;
    const float* b1o = b1 + o * HID;
    float acc = 0.f;
    for (int k = 0; k < HID; k++)
        acc = fmaf(fmaxf(b1o[k], 0.f), w2o[(size_t)k * DMODEL + n], acc);
    g_bias2[i] = b2[e * DMODEL + n] + b2[o * DMODEL + n] + sb2[n] + acc;
}

// ------------------------------------------------------------------
// 128x256x32 fp16 mma.sync m16n8k16 GEMM: 8 warps (2m x 4n), 64x64 warp
// tiles, ldmatrix.x4 fragments, 4-stage cp.async pipeline.
// Per warp-ktile: 16 LDSM + 64 MMA (half the HMMA count of the tf32 path).
template <int K, int NT, bool G1>
__global__ void __launch_bounds__(256, 1)
gemm_cp(float* __restrict__ out_g2) {
    // CTA raster swizzle: groups of 16 m-tiles, m fastest
    const int bid = blockIdx.y * gridDim.x + blockIdx.x;
    const int per = gridDim.x * 16;
    const int mt  = (bid / per) * 16 + (bid % 16);
    const int j   = (bid % per) >> 4;

    const int c0 = g_counts[0];
    const int c1 = N_TOK - c0;
    const int t0 = (c0 + BM - 1) / BM;
    const int t1 = (c1 + BM - 1) / BM;
    int expert, row0, valid;
    if (mt < t0)           { expert = 0; row0 = mt * BM;            valid = min(BM, c0 - row0); }
    else if (mt - t0 < t1) { int t = mt - t0; expert = 1; row0 = c0 + t * BM; valid = min(BM, c1 - t * BM); }
    else return;

    const __half* __restrict__ A    = G1 ? g_xr : g_h;
    const __half* __restrict__ Bt   = G1 ? g_B1 : g_B2;
    const float*  __restrict__ bias = G1 ? g_bias1 : g_bias2;
    const int n0 = j * BN;
    const __half* __restrict__ Bp = Bt + ((size_t)expert * NT + n0) * K;

    extern __shared__ __half smem[];
    __half* sA = smem;                     // [STAGES][BM][LDK]
    __half* sB = smem + STAGES * A_STG;    // [STAGES][BN][LDK]
    const uint32_t sAu = (uint32_t)__cvta_generic_to_shared(sA);
    const uint32_t sBu = (uint32_t)__cvta_generic_to_shared(sB);

    const int tid = threadIdx.x, lane = tid & 31, warp = tid >> 5;
    const int wm = warp & 1;    // 2 warps over M (64 rows)
    const int wn = warp >> 1;   // 4 warps over N (64 cols)

    // per-stage fill: A 128x32 fp16 (2x16B/thr), B 256x32 fp16 (4x16B/thr)
    auto load_tile = [&](int kt, int stage) {
        const int kof = kt * BK;
        const uint32_t aB = sAu + stage * (A_STG * 2);
        const uint32_t bB = sBu + stage * (B_STG * 2);
        #pragma unroll
        for (int p = 0; p < 2; p++) {
            int idx = tid + p * 256;             // 0..511 ; 4 chunks per 32-h row
            int r = idx >> 2, c8 = idx & 3;
            int rg = row0 + r; if (rg > N_TOK - 1) rg = N_TOK - 1;
            cp_async16(aB + (uint32_t)(r * (LDK * 2) + c8 * 16),
                       A + (size_t)rg * K + kof + c8 * 8);
        }
        #pragma unroll
        for (int p = 0; p < 4; p++) {
            int idx = tid + p * 256;             // 0..1023
            int r = idx >> 2, c8 = idx & 3;
            cp_async16(bB + (uint32_t)(r * (LDK * 2) + c8 * 16),
                       Bp + (size_t)r * K + kof + c8 * 8);
        }
        CP_COMMIT();
    };

    constexpr int KT = K / BK;
    load_tile(0, 0);
    load_tile(1, 1);
    load_tile(2, 2);

    float4 acc[4][8];
    #pragma unroll
    for (int i = 0; i < 4; i++)
        #pragma unroll
        for (int jn = 0; jn < 8; jn++)
            acc[i][jn] = make_float4(0.f, 0.f, 0.f, 0.f);

    // ldmatrix per-thread addressing (fp16, 8x8 b16 matrices)
    //   A m16k16: row = lane%16, k-half = lane/16  -> a0..a3 in mma order
    //   B pair n16k16: matrices {n0-7,k0-7},{n0-7,k8-15},{n8-15,k0-7},{n8-15,k8-15}
    const int mA = lane & 15;
    const int kA = (lane >> 4) * 8;
    const int nB = (lane & 7) + ((lane >> 4) << 3);
    const int kB = ((lane >> 3) & 1) * 8;
    const uint32_t aBase = sAu + (uint32_t)(((wm * 64 + mA) * LDK + kA) * 2);
    const uint32_t bBase = sBu + (uint32_t)(((wn * 64 + nB) * LDK + kB) * 2);

    #pragma unroll 1
    for (int kt = 0; kt < KT; kt++) {
        CP_WAIT2();
        __syncthreads();
        if (kt + 3 < KT) load_tile(kt + 3, (kt + 3) & (STAGES - 1));
        else             CP_COMMIT();        // keep group counting uniform

        const uint32_t aS = aBase + (uint32_t)((kt & (STAGES - 1)) * (A_STG * 2));
        const uint32_t bS = bBase + (uint32_t)((kt & (STAGES - 1)) * (B_STG * 2));
        #pragma unroll
        for (int ks = 0; ks < 2; ks++) {     // two k16 steps per 32-k tile
            uint32_t af[4][4], bf[4][4];
            #pragma unroll
            for (int m = 0; m < 4; m++)
                LDSM4(af[m], aS + (uint32_t)(m * (16 * LDK * 2) + ks * 32));
            #pragma unroll
            for (int np = 0; np < 4; np++)
                LDSM4(bf[np], bS + (uint32_t)(np * (16 * LDK * 2) + ks * 32));
            #pragma unroll
            for (int m = 0; m < 4; m++)
                #pragma unroll
                for (int nt = 0; nt < 8; nt++)
                    mma_f16(acc[m][nt], af[m], &bf[nt >> 1][(nt & 1) * 2]);
        }
    }

    // epilogue
    const float* bv = bias + (size_t)expert * NT + n0;
    const int grow = lane >> 2;
    const int gc   = (lane & 3) << 1;
    #pragma unroll
    for (int m = 0; m < 4; m++) {
        int rl = wm * 64 + m * 16 + grow;
        #pragma unroll
        for (int nt = 0; nt < 8; nt++) {
            int cl = wn * 64 + nt * 8 + gc;
            float bb0 = bv[cl], bb1 = bv[cl + 1];
            float v00 = acc[m][nt].x + bb0;
            float v01 = acc[m][nt].y + bb1;
            float v10 = acc[m][nt].z + bb0;
            float v11 = acc[m][nt].w + bb1;
            if constexpr (G1) {
                if (rl < valid) {
                    __half2 v = __floats2half2_rn(fmaxf(v00, 0.f), fmaxf(v01, 0.f));
                    *reinterpret_cast<__half2*>(&g_h[(size_t)(row0 + rl) * HCAT + n0 + cl]) = v;
                }
                if (rl + 8 < valid) {
                    __half2 v = __floats2half2_rn(fmaxf(v10, 0.f), fmaxf(v11, 0.f));
                    *reinterpret_cast<__half2*>(&g_h[(size_t)(row0 + rl + 8) * HCAT + n0 + cl]) = v;
                }
            } else {
                if (rl < valid) {
                    int orow = g_perm[row0 + rl];
                    float2 v = {v00, v01};
                    *reinterpret_cast<float2*>(&out_g2[(size_t)orow * DMODEL + n0 + cl]) = v;
                }
                if (rl + 8 < valid) {
                    int orow = g_perm[row0 + rl + 8];
                    float2 v = {v10, v11};
                    *reinterpret_cast<float2*>(&out_g2[(size_t)orow * DMODEL + n0 + cl]) = v;
                }
            }
        }
    }
}

// ---------------- launch ----------------
extern "C" void kernel_launch(void* const* d_in, const int* in_sizes, int n_in,
                              void* d_out, int out_size) {
    const float* x   = (const float*)d_in[0];
    const float* gw  = (const float*)d_in[1];
    const float* w1  = (const float*)d_in[2];
    const float* b1  = (const float*)d_in[3];
    const float* w2  = (const float*)d_in[4];
    const float* b2  = (const float*)d_in[5];
    const float* sw1 = (const float*)d_in[6];
    const float* sb1 = (const float*)d_in[7];
    const float* sw2 = (const float*)d_in[8];
    const float* sb2 = (const float*)d_in[9];
    float* out = (float*)d_out;

    cudaFuncSetAttribute((const void*)gemm_cp<DMODEL, HCAT, true>,
                         cudaFuncAttributeMaxDynamicSharedMemorySize, GEMM_SMEM);
    cudaFuncSetAttribute((const void*)gemm_cp<HCAT, DMODEL, false>,
                         cudaFuncAttributeMaxDynamicSharedMemorySize, GEMM_SMEM);

    zero_kernel<<<1, 32>>>();
    gate_kernel<<<N_TOK / 8, 256>>>(x, gw);
    scatter_kernel<<<N_TOK / 256, 256>>>();
    prep_x_kernel<<<2048, 256>>>(x);
    prep_B1t_kernel<<<dim3(HCAT / 32, DMODEL / 32, 2), 256>>>(w1, sw1);
    prep_B2t_kernel<<<dim3(DMODEL / 32, HCAT / 32, 2), 256>>>(w2, sw2);
    prep_bias1_kernel<<<(2 * HCAT) / 256, 256>>>(b1, sb1);
    prep_bias2_kernel<<<(2 * DMODEL) / 256, 256>>>(b1, b2, w2, sb2);

    // 129 m-tiles padded to 144 (9 swizzle groups of 16); extras exit early
    gemm_cp<DMODEL, HCAT, true ><<<dim3(HCAT / BN,   144), 256, GEMM_SMEM>>>(nullptr);
    gemm_cp<HCAT, DMODEL, false><<<dim3(DMODEL / BN, 144), 256, GEMM_SMEM>>>(out);
}

// round 17
// speedup vs baseline: 1.7697x; 1.1726x over previous
#include <cuda_runtime.h>
#include <cuda_fp16.h>
#include <cstdint>

// DeepSeekMoEFFN (sm_103 plain PTX: no tcgen05) — fp16 mma.sync m16n8k16
// GEMMs (fp32 accumulate), ldmatrix fragments, 4-stage cp.async pipeline.
// R15: gate demoted from bulk-fp64 to fp32 partials (fp64 reduction only);
//      prep_bias2 parallelized (two-phase k-split reduction).
//
//  1. gate (fp32 dot, fp64 reduce, argmax) -> expert ids + counts
//  2. counting-sort -> perm
//  3. prep: gather x -> fp16; transpose weights to K-major [e][n][k] fp16;
//     bias1=[b1_e|sb1]; bias2 = b2_0+b2_1+sb2+relu(b1_o)@w2_o   (fp32)
//  4. GEMM1: h = fp16(relu(xs @ B1_e + bias1_e))   [16384 x 8192]
//  5. GEMM2: out[perm] = h @ B2_e + bias2_e        [16384 x 1024] fp32

#define N_TOK  16384
#define DMODEL 1024
#define HID    4096
#define HCAT   8192

#define BM 128
#define BN 256
#define BK 32
#define STAGES 4
#define LDK 40                        // padded k-stride in halves (80 B rows)
#define A_STG (BM * LDK)              // halves
#define B_STG (BN * LDK)              // halves
#define GEMM_SMEM (STAGES * (A_STG + B_STG) * 2)   // 122880 B

#define B2_KCH 32                     // k-chunks for bias2 partial reduction

// ---- static device scratch ----
__device__ __half g_h [(size_t)N_TOK * HCAT];       // fp16 intermediate (256MB)
__device__ __half g_xr[(size_t)N_TOK * DMODEL];     // sorted fp16 x
__device__ __half g_B1[(size_t)2 * HCAT * DMODEL];  // [e][n][k] K-major fp16
__device__ __half g_B2[(size_t)2 * DMODEL * HCAT];  // [e][n][k] K-major fp16
__device__ float  g_bias1[2 * HCAT];
__device__ float  g_bias2[2 * DMODEL];
__device__ float  g_b2part[2][B2_KCH][DMODEL];
__device__ int    g_expert[N_TOK];
__device__ int    g_perm[N_TOK];
__device__ int    g_counts[2];
__device__ int    g_cursor[2];

// ---------------- helpers ----------------
__device__ __forceinline__ void mma_f16(float4& d, const uint32_t* a, const uint32_t* b) {
    asm volatile(
        "mma.sync.aligned.m16n8k16.row.col.f32.f16.f16.f32 "
        "{%0,%1,%2,%3}, {%4,%5,%6,%7}, {%8,%9}, {%0,%1,%2,%3};"
        : "+f"(d.x), "+f"(d.y), "+f"(d.z), "+f"(d.w)
        : "r"(a[0]), "r"(a[1]), "r"(a[2]), "r"(a[3]),
          "r"(b[0]), "r"(b[1]));
}
__device__ __forceinline__ void cp_async16(uint32_t s, const void* g) {
    asm volatile("cp.async.cg.shared.global [%0], [%1], 16;" :: "r"(s), "l"(g));
}
#define CP_COMMIT() asm volatile("cp.async.commit_group;" ::: "memory")
#define CP_WAIT2()  asm volatile("cp.async.wait_group 2;" ::: "memory")
#define LDSM4(r, a) \
    asm volatile("ldmatrix.sync.aligned.m8n8.x4.shared.b16 {%0,%1,%2,%3}, [%4];" \
        : "=r"((r)[0]), "=r"((r)[1]), "=r"((r)[2]), "=r"((r)[3]) : "r"(a))

// ---------------- routing / prep ----------------
__global__ void zero_kernel() {
    if (threadIdx.x == 0) { g_counts[0] = g_counts[1] = 0; g_cursor[0] = g_cursor[1] = 0; }
}

// one warp per token; fp32 per-lane partials (err ~1e-7 on score gap ~0.58 ->
// flip prob ~2e-7/token), fp64 only for the 5-level reduction.
__global__ void gate_kernel(const float* __restrict__ x, const float* __restrict__ gw) {
    int t = blockIdx.x * (blockDim.x >> 5) + (threadIdx.x >> 5);
    if (t >= N_TOK) return;
    int lane = threadIdx.x & 31;
    const float4* xr = reinterpret_cast<const float4*>(x + (size_t)t * DMODEL);
    const float4* g0 = reinterpret_cast<const float4*>(gw);
    const float4* g1 = reinterpret_cast<const float4*>(gw + DMODEL);
    float s0 = 0.f, s1 = 0.f;
    #pragma unroll
    for (int i = 0; i < 8; i++) {
        int c = lane + i * 32;             // 256 float4 per row
        float4 xv = xr[c], a = g0[c], b = g1[c];
        s0 += xv.x * a.x + xv.y * a.y + xv.z * a.z + xv.w * a.w;
        s1 += xv.x * b.x + xv.y * b.y + xv.z * b.z + xv.w * b.w;
    }
    double d0 = (double)s0, d1 = (double)s1;
    #pragma unroll
    for (int o = 16; o > 0; o >>= 1) {
        d0 += __shfl_down_sync(0xffffffffu, d0, o);
        d1 += __shfl_down_sync(0xffffffffu, d1, o);
    }
    if (lane == 0) {
        int e = (d1 > d0) ? 1 : 0;
        g_expert[t] = e;
        atomicAdd(&g_counts[e], 1);
    }
}

__global__ void scatter_kernel() {
    int t = blockIdx.x * blockDim.x + threadIdx.x;
    if (t >= N_TOK) return;
    int e = g_expert[t];
    int base = e ? g_counts[0] : 0;
    g_perm[base + atomicAdd(&g_cursor[e], 1)] = t;
}

__global__ void prep_x_kernel(const float* __restrict__ x) {
    const float4* x4 = reinterpret_cast<const float4*>(x);
    __half2* d2 = reinterpret_cast<__half2*>(g_xr);
    const int total = N_TOK * (DMODEL / 4);
    for (int i = blockIdx.x * blockDim.x + threadIdx.x; i < total;
         i += gridDim.x * blockDim.x) {
        int pos = i >> 8, c4 = i & 255;
        int src = g_perm[pos];
        float4 v = x4[(size_t)src * 256 + c4];
        d2[2 * i]     = __floats2half2_rn(v.x, v.y);
        d2[2 * i + 1] = __floats2half2_rn(v.z, v.w);
    }
}

// B1t[e][n][k] = fp16( n<HID ? w1[e][k][n] : sw1[k][n-HID] )
__global__ void prep_B1t_kernel(const float* __restrict__ w1, const float* __restrict__ sw1) {
    __shared__ float t[32][33];
    int n0 = blockIdx.x * 32, k0 = blockIdx.y * 32, e = blockIdx.z;
    int tx = threadIdx.x & 31, ty = threadIdx.x >> 5;
    int n = n0 + tx;
    #pragma unroll
    for (int p = 0; p < 4; p++) {
        int k = k0 + ty + p * 8;
        float v = (n < HID) ? w1[((size_t)e * DMODEL + k) * HID + n]
                            : sw1[(size_t)k * HID + (n - HID)];
        t[ty + p * 8][tx] = v;
    }
    __syncthreads();
    #pragma unroll
    for (int p = 0; p < 4; p++) {
        int ni = ty + p * 8;
        g_B1[((size_t)e * HCAT + n0 + ni) * DMODEL + k0 + tx] = __float2half_rn(t[tx][ni]);
    }
}

// B2t[e][n][k] = fp16( k<HID ? w2[e][k][n] : sw2[k-HID][n] )
__global__ void prep_B2t_kernel(const float* __restrict__ w2, const float* __restrict__ sw2) {
    __shared__ float t[32][33];
    int n0 = blockIdx.x * 32, k0 = blockIdx.y * 32, e = blockIdx.z;
    int tx = threadIdx.x & 31, ty = threadIdx.x >> 5;
    int n = n0 + tx;
    #pragma unroll
    for (int p = 0; p < 4; p++) {
        int k = k0 + ty + p * 8;
        float v = (k < HID) ? w2[((size_t)e * HID + k) * DMODEL + n]
                            : sw2[(size_t)(k - HID) * DMODEL + n];
        t[ty + p * 8][tx] = v;
    }
    __syncthreads();
    #pragma unroll
    for (int p = 0; p < 4; p++) {
        int ni = ty + p * 8;
        g_B2[((size_t)e * DMODEL + n0 + ni) * HCAT + k0 + tx] = __float2half_rn(t[tx][ni]);
    }
}

__global__ void prep_bias1_kernel(const float* __restrict__ b1, const float* __restrict__ sb1) {
    int i = blockIdx.x * blockDim.x + threadIdx.x;
    if (i >= 2 * HCAT) return;
    int e = i >> 13, n = i & (HCAT - 1);
    g_bias1[i] = (n < HID) ? b1[e * HID + n] : sb1[n - HID];
}

// phase 1: partial[e][kc][n] = sum_{k in chunk} relu(b1[1-e][k]) * w2[1-e][k][n]
// block = (kc, e), 1024 threads = one per n; coalesced w2 rows.
__global__ void prep_bias2_part_kernel(const float* __restrict__ b1,
                                       const float* __restrict__ w2) {
    const int kc = blockIdx.x, e = blockIdx.y;
    const int n = threadIdx.x;                 // DMODEL threads
    const int o = 1 - e;
    const float* w2o = w2 + (size_t)o * HID * DMODEL;
    const float* b1o = b1 + o * HID;
    constexpr int KPC = HID / B2_KCH;          // 128
    float acc = 0.f;
    #pragma unroll 4
    for (int kk = 0; kk < KPC; kk++) {
        int k = kc * KPC + kk;
        acc = fmaf(fmaxf(b1o[k], 0.f), w2o[(size_t)k * DMODEL + n], acc);
    }
    g_b2part[e][kc][n] = acc;
}

// phase 2: bias2[e][n] = b2[e][n] + b2[1-e][n] + sb2[n] + sum_kc partial
__global__ void prep_bias2_final_kernel(const float* __restrict__ b2,
                                        const float* __restrict__ sb2) {
    int i = blockIdx.x * blockDim.x + threadIdx.x;
    if (i >= 2 * DMODEL) return;
    int e = i >> 10, n = i & (DMODEL - 1);
    int o = 1 - e;
    float acc = 0.f;
    #pragma unroll
    for (int kc = 0; kc < B2_KCH; kc++) acc += g_b2part[e][kc][n];
    g_bias2[i] = b2[e * DMODEL + n] + b2[o * DMODEL + n] + sb2[n] + acc;
}

// ------------------------------------------------------------------
// 128x256x32 fp16 mma.sync m16n8k16 GEMM: 8 warps (2m x 4n), 64x64 warp
// tiles, ldmatrix.x4 fragments, 4-stage cp.async pipeline.
template <int K, int NT, bool G1>
__global__ void __launch_bounds__(256, 1)
gemm_cp(float* __restrict__ out_g2) {
    // CTA raster swizzle: groups of 16 m-tiles, m fastest
    const int bid = blockIdx.y * gridDim.x + blockIdx.x;
    const int per = gridDim.x * 16;
    const int mt  = (bid / per) * 16 + (bid % 16);
    const int j   = (bid % per) >> 4;

    const int c0 = g_counts[0];
    const int c1 = N_TOK - c0;
    const int t0 = (c0 + BM - 1) / BM;
    const int t1 = (c1 + BM - 1) / BM;
    int expert, row0, valid;
    if (mt < t0)           { expert = 0; row0 = mt * BM;            valid = min(BM, c0 - row0); }
    else if (mt - t0 < t1) { int t = mt - t0; expert = 1; row0 = c0 + t * BM; valid = min(BM, c1 - t * BM); }
    else return;

    const __half* __restrict__ A    = G1 ? g_xr : g_h;
    const __half* __restrict__ Bt   = G1 ? g_B1 : g_B2;
    const float*  __restrict__ bias = G1 ? g_bias1 : g_bias2;
    const int n0 = j * BN;
    const __half* __restrict__ Bp = Bt + ((size_t)expert * NT + n0) * K;

    extern __shared__ __half smem[];
    __half* sA = smem;                     // [STAGES][BM][LDK]
    __half* sB = smem + STAGES * A_STG;    // [STAGES][BN][LDK]
    const uint32_t sAu = (uint32_t)__cvta_generic_to_shared(sA);
    const uint32_t sBu = (uint32_t)__cvta_generic_to_shared(sB);

    const int tid = threadIdx.x, lane = tid & 31, warp = tid >> 5;
    const int wm = warp & 1;    // 2 warps over M (64 rows)
    const int wn = warp >> 1;   // 4 warps over N (64 cols)

    // per-stage fill: A 128x32 fp16 (2x16B/thr), B 256x32 fp16 (4x16B/thr)
    auto load_tile = [&](int kt, int stage) {
        const int kof = kt * BK;
        const uint32_t aB = sAu + stage * (A_STG * 2);
        const uint32_t bB = sBu + stage * (B_STG * 2);
        #pragma unroll
        for (int p = 0; p < 2; p++) {
            int idx = tid + p * 256;             // 0..511 ; 4 chunks per 32-h row
            int r = idx >> 2, c8 = idx & 3;
            int rg = row0 + r; if (rg > N_TOK - 1) rg = N_TOK - 1;
            cp_async16(aB + (uint32_t)(r * (LDK * 2) + c8 * 16),
                       A + (size_t)rg * K + kof + c8 * 8);
        }
        #pragma unroll
        for (int p = 0; p < 4; p++) {
            int idx = tid + p * 256;             // 0..1023
            int r = idx >> 2, c8 = idx & 3;
            cp_async16(bB + (uint32_t)(r * (LDK * 2) + c8 * 16),
                       Bp + (size_t)r * K + kof + c8 * 8);
        }
        CP_COMMIT();
    };

    constexpr int KT = K / BK;
    load_tile(0, 0);
    load_tile(1, 1);
    load_tile(2, 2);

    float4 acc[4][8];
    #pragma unroll
    for (int i = 0; i < 4; i++)
        #pragma unroll
        for (int jn = 0; jn < 8; jn++)
            acc[i][jn] = make_float4(0.f, 0.f, 0.f, 0.f);

    // ldmatrix per-thread addressing (fp16, 8x8 b16 matrices)
    const int mA = lane & 15;
    const int kA = (lane >> 4) * 8;
    const int nB = (lane & 7) + ((lane >> 4) << 3);
    const int kB = ((lane >> 3) & 1) * 8;
    const uint32_t aBase = sAu + (uint32_t)(((wm * 64 + mA) * LDK + kA) * 2);
    const uint32_t bBase = sBu + (uint32_t)(((wn * 64 + nB) * LDK + kB) * 2);

    #pragma unroll 1
    for (int kt = 0; kt < KT; kt++) {
        CP_WAIT2();
        __syncthreads();
        if (kt + 3 < KT) load_tile(kt + 3, (kt + 3) & (STAGES - 1));
        else             CP_COMMIT();        // keep group counting uniform

        const uint32_t aS = aBase + (uint32_t)((kt & (STAGES - 1)) * (A_STG * 2));
        const uint32_t bS = bBase + (uint32_t)((kt & (STAGES - 1)) * (B_STG * 2));
        #pragma unroll
        for (int ks = 0; ks < 2; ks++) {     // two k16 steps per 32-k tile
            uint32_t af[4][4], bf[4][4];
            #pragma unroll
            for (int m = 0; m < 4; m++)
                LDSM4(af[m], aS + (uint32_t)(m * (16 * LDK * 2) + ks * 32));
            #pragma unroll
            for (int np = 0; np < 4; np++)
                LDSM4(bf[np], bS + (uint32_t)(np * (16 * LDK * 2) + ks * 32));
            #pragma unroll
            for (int m = 0; m < 4; m++)
                #pragma unroll
                for (int nt = 0; nt < 8; nt++)
                    mma_f16(acc[m][nt], af[m], &bf[nt >> 1][(nt & 1) * 2]);
        }
    }

    // epilogue
    const float* bv = bias + (size_t)expert * NT + n0;
    const int grow = lane >> 2;
    const int gc   = (lane & 3) << 1;
    #pragma unroll
    for (int m = 0; m < 4; m++) {
        int rl = wm * 64 + m * 16 + grow;
        #pragma unroll
        for (int nt = 0; nt < 8; nt++) {
            int cl = wn * 64 + nt * 8 + gc;
            float bb0 = bv[cl], bb1 = bv[cl + 1];
            float v00 = acc[m][nt].x + bb0;
            float v01 = acc[m][nt].y + bb1;
            float v10 = acc[m][nt].z + bb0;
            float v11 = acc[m][nt].w + bb1;
            if constexpr (G1) {
                if (rl < valid) {
                    __half2 v = __floats2half2_rn(fmaxf(v00, 0.f), fmaxf(v01, 0.f));
                    *reinterpret_cast<__half2*>(&g_h[(size_t)(row0 + rl) * HCAT + n0 + cl]) = v;
                }
                if (rl + 8 < valid) {
                    __half2 v = __floats2half2_rn(fmaxf(v10, 0.f), fmaxf(v11, 0.f));
                    *reinterpret_cast<__half2*>(&g_h[(size_t)(row0 + rl + 8) * HCAT + n0 + cl]) = v;
                }
            } else {
                if (rl < valid) {
                    int orow = g_perm[row0 + rl];
                    float2 v = {v00, v01};
                    *reinterpret_cast<float2*>(&out_g2[(size_t)orow * DMODEL + n0 + cl]) = v;
                }
                if (rl + 8 < valid) {
                    int orow = g_perm[row0 + rl + 8];
                    float2 v = {v10, v11};
                    *reinterpret_cast<float2*>(&out_g2[(size_t)orow * DMODEL + n0 + cl]) = v;
                }
            }
        }
    }
}

// ---------------- launch ----------------
extern "C" void kernel_launch(void* const* d_in, const int* in_sizes, int n_in,
                              void* d_out, int out_size) {
    const float* x   = (const float*)d_in[0];
    const float* gw  = (const float*)d_in[1];
    const float* w1  = (const float*)d_in[2];
    const float* b1  = (const float*)d_in[3];
    const float* w2  = (const float*)d_in[4];
    const float* b2  = (const float*)d_in[5];
    const float* sw1 = (const float*)d_in[6];
    const float* sb1 = (const float*)d_in[7];
    const float* sw2 = (const float*)d_in[8];
    const float* sb2 = (const float*)d_in[9];
    float* out = (float*)d_out;

    cudaFuncSetAttribute((const void*)gemm_cp<DMODEL, HCAT, true>,
                         cudaFuncAttributeMaxDynamicSharedMemorySize, GEMM_SMEM);
    cudaFuncSetAttribute((const void*)gemm_cp<HCAT, DMODEL, false>,
                         cudaFuncAttributeMaxDynamicSharedMemorySize, GEMM_SMEM);

    zero_kernel<<<1, 32>>>();
    gate_kernel<<<N_TOK / 8, 256>>>(x, gw);
    scatter_kernel<<<N_TOK / 256, 256>>>();
    prep_x_kernel<<<2048, 256>>>(x);
    prep_B1t_kernel<<<dim3(HCAT / 32, DMODEL / 32, 2), 256>>>(w1, sw1);
    prep_B2t_kernel<<<dim3(DMODEL / 32, HCAT / 32, 2), 256>>>(w2, sw2);
    prep_bias1_kernel<<<(2 * HCAT) / 256, 256>>>(b1, sb1);
    prep_bias2_part_kernel<<<dim3(B2_KCH, 2), DMODEL>>>(b1, w2);
    prep_bias2_final_kernel<<<(2 * DMODEL) / 256, 256>>>(b2, sb2);

    // 129 m-tiles padded to 144 (9 swizzle groups of 16); extras exit early
    gemm_cp<DMODEL, HCAT, true ><<<dim3(HCAT / BN,   144), 256, GEMM_SMEM>>>(nullptr);
    gemm_cp<HCAT, DMODEL, false><<<dim3(DMODEL / BN, 144), 256, GEMM_SMEM>>>(out);
}